// round 13
// baseline (speedup 1.0000x reference)
#include <cuda_runtime.h>
#include <cuda_fp16.h>
#include <cstdint>

// ============================================================================
// SubtractionGaussian: out[b,h,i,j] = ||q_i||^2 + ||k_j||^2 - 2 q_i . k_j
// B*H = 32, Lq = Lk = 2048, D = 64, fp32 in/out.
//
// R13 = R12 (64x64 warp tiles, fp16 acc, 2 CTAs/SM) + software-pipelined
//       epilogue: 4 rotating stage buffers/warp, 1 syncwarp/slab, LDS of
//       slab s overlapped with STS of slab s+1. Phases unchanged; goal is
//       re-saturating L1 at 16 warps.
// ============================================================================

#define LQ 2048
#define LK 2048
#define DDIM 64
#define TM 128
#define TN 256
#define SUBN 128
#define THREADS 256

#define QROW 72         // halfs per Qs row (9 granules == 1 mod 8 -> ldmatrix conflict-free)
#define KROW 264        // halfs per Ks row (33 granules == 1 mod 8 -> conflict-free)
#define SWORDS 72       // stage super-row pitch in words (== 8 mod 32 -> STS conflict-free)
#define BUFW   (4 * SWORDS)   // words per stage buffer (4 super-rows)

// dynamic smem layout (bytes)
#define OFF_QS   0                        // 128*72*2  = 18432
#define OFF_KS   18432                    // 64*264*2  = 33792
#define OFF_STG  52224                    // 8 warps * 4 bufs * 1152B = 36864 (kpart aliases)
#define OFF_Q2   89088                    // 128*4     = 512
#define OFF_K2   89600                    // 256*4     = 1024
#define SMEM_TOTAL 90624

// f16-accum MMA: D,C are 2 regs of half2. Chained D=C.
__device__ __forceinline__ void mma16816_f16(uint32_t* d, const uint32_t* a,
                                             uint32_t b0, uint32_t b1) {
    asm volatile(
        "mma.sync.aligned.m16n8k16.row.col.f16.f16.f16.f16 "
        "{%0,%1}, {%2,%3,%4,%5}, {%6,%7}, {%0,%1};"
        : "+r"(d[0]), "+r"(d[1])
        : "r"(a[0]), "r"(a[1]), "r"(a[2]), "r"(a[3]), "r"(b0), "r"(b1));
}

__device__ __forceinline__ void ldmatrix_x4(uint32_t* r, uint32_t addr) {
    asm volatile("ldmatrix.sync.aligned.m8n8.x4.shared.b16 {%0,%1,%2,%3}, [%4];"
                 : "=r"(r[0]), "=r"(r[1]), "=r"(r[2]), "=r"(r[3]) : "r"(addr));
}

__device__ __forceinline__ void ldmatrix_x4_trans(uint32_t* r, uint32_t addr) {
    asm volatile("ldmatrix.sync.aligned.m8n8.x4.trans.shared.b16 {%0,%1,%2,%3}, [%4];"
                 : "=r"(r[0]), "=r"(r[1]), "=r"(r[2]), "=r"(r[3]) : "r"(addr));
}

__global__ void __launch_bounds__(THREADS, 2)
subgauss_kernel(const float* __restrict__ q,   // [BH, Lq, D]
                const float* __restrict__ k,   // [BH, D, Lk]
                float* __restrict__ out)       // [BH, Lq, Lk]
{
    extern __shared__ __align__(16) char smem[];
    __half* Qs = reinterpret_cast<__half*>(smem + OFF_QS);       // [TM][QROW]
    __half* Ks = reinterpret_cast<__half*>(smem + OFF_KS);       // [DDIM][KROW], holds -2k
    uint32_t* stgall = reinterpret_cast<uint32_t*>(smem + OFF_STG);
    float* kpart = reinterpret_cast<float*>(smem + OFF_STG);     // alias: dead before stage use
    float* q2s = reinterpret_cast<float*>(smem + OFF_Q2);        // [TM]
    float* k2s = reinterpret_cast<float*>(smem + OFF_K2);        // [TN]

    const int tid = threadIdx.x;
    const int lane = tid & 31;
    const int wid = tid >> 5;

    const int bh = blockIdx.z;
    const int i0 = blockIdx.y * TM;
    const int j0 = blockIdx.x * TN;

    // ---- Q load: 128 rows; 2 rows per warp-inst (16 lanes x float4). ----
    {
        const int hi = lane >> 4;
        const int seg2 = lane & 15;
#pragma unroll
        for (int p = 0; p < 8; p++) {
            const int r = wid * 2 + hi + p * 16;
            const float* qrow = q + ((size_t)bh * LQ + (size_t)(i0 + r)) * DDIM;
            float4 v = *reinterpret_cast<const float4*>(qrow + seg2 * 4);
            float s = v.x * v.x + v.y * v.y + v.z * v.z + v.w * v.w;
            s += __shfl_down_sync(0xffffffffu, s, 8, 16);
            s += __shfl_down_sync(0xffffffffu, s, 4, 16);
            s += __shfl_down_sync(0xffffffffu, s, 2, 16);
            s += __shfl_down_sync(0xffffffffu, s, 1, 16);
            if (seg2 == 0) q2s[r] = s;
            __half2 h01 = __floats2half2_rn(v.x, v.y);
            __half2 h23 = __floats2half2_rn(v.z, v.w);
            uint2 u;
            u.x = *reinterpret_cast<uint32_t*>(&h01);
            u.y = *reinterpret_cast<uint32_t*>(&h23);
            *reinterpret_cast<uint2*>(&Qs[r * QROW + seg2 * 4]) = u;
        }
    }

    // ---- K load: 256 cols (two halves); Ks holds -2k; exact fp32 k2 partials. ----
#pragma unroll
    for (int jt = 0; jt < 2; jt++) {
        const float* kb = k + (size_t)bh * DDIM * LK + (size_t)(j0 + jt * SUBN) + lane * 4;
        float4 ksum = make_float4(0.f, 0.f, 0.f, 0.f);
#pragma unroll
        for (int p = 0; p < 8; p++) {
            const int c = wid + p * 8;
            float4 v = *reinterpret_cast<const float4*>(kb + (size_t)c * LK);
            ksum.x += v.x * v.x; ksum.y += v.y * v.y;
            ksum.z += v.z * v.z; ksum.w += v.w * v.w;
            __half2 h01 = __floats2half2_rn(-2.0f * v.x, -2.0f * v.y);
            __half2 h23 = __floats2half2_rn(-2.0f * v.z, -2.0f * v.w);
            uint2 u;
            u.x = *reinterpret_cast<uint32_t*>(&h01);
            u.y = *reinterpret_cast<uint32_t*>(&h23);
            *reinterpret_cast<uint2*>(&Ks[c * KROW + jt * SUBN + lane * 4]) = u;
        }
        *reinterpret_cast<float4*>(&kpart[wid * TN + jt * SUBN + lane * 4]) = ksum;
    }
    __syncthreads();

    // ---- k2 reduce: 256 threads, exact fp32 (kpart region dies here). ----
    {
        float s = 0.0f;
#pragma unroll
        for (int w = 0; w < 8; w++) s += kpart[w * TN + tid];
        k2s[tid] = s;
    }
    __syncthreads();
    // -------- no CTA-wide barriers below this line --------

    // ---- Warp tile 64x64: 2 M-groups x 4 N-groups. ----
    const int wm = wid & 1;
    const int wn = wid >> 1;
    const int mbase = wm * 64;
    const int nbase = wn * 64;
    const int g = lane >> 3;      // ldmatrix quadrant
    const int lr = lane & 7;      // ldmatrix row

    uint32_t acc[4][8][2];
#pragma unroll
    for (int mm = 0; mm < 4; mm++)
#pragma unroll
        for (int nn = 0; nn < 8; nn++) {
            acc[mm][nn][0] = 0u;
            acc[mm][nn][1] = 0u;
        }

    // ---- Mainloop: fp16 accumulate; acc = -2*q.k (K pre-scaled). ----
#pragma unroll
    for (int ks = 0; ks < 4; ks++) {
        uint32_t A[4][4];
#pragma unroll
        for (int mm = 0; mm < 4; mm++) {
            uint32_t addr = (uint32_t)__cvta_generic_to_shared(
                &Qs[(mbase + mm * 16 + (g & 1) * 8 + lr) * QROW
                    + ks * 16 + (g >> 1) * 8]);
            ldmatrix_x4(A[mm], addr);
        }
#pragma unroll
        for (int e = 0; e < 4; e++) {
            uint32_t B[4];
            uint32_t addr = (uint32_t)__cvta_generic_to_shared(
                &Ks[(ks * 16 + (g & 1) * 8 + lr) * KROW
                    + nbase + e * 16 + (g >> 1) * 8]);
            ldmatrix_x4_trans(B, addr);
#pragma unroll
            for (int mm = 0; mm < 4; mm++) {
                mma16816_f16(acc[mm][2 * e],     A[mm], B[0], B[1]);
                mma16816_f16(acc[mm][2 * e + 1], A[mm], B[2], B[3]);
            }
        }
    }

    // ---- Pipelined epilogue: 8 slabs (s = mm*2 + h), 4 rotating buffers. ----
    uint32_t* bufs = stgall + wid * 4 * BUFW;   // warp-private, 4 buffers
    // writer roles
    const int tq = lane & 3;
    const int sw = (lane >> 2) >> 1;     // super-row
    const int e0 = (lane >> 2) & 1;      // row parity
    const uint32_t psel = e0 ? 0x3276u : 0x5410u;
    // reader roles
    const int sr = lane >> 3;
    const int j8 = lane & 7;

    float4 k2A = *reinterpret_cast<const float4*>(&k2s[nbase + j8 * 4]);
    float4 k2B = *reinterpret_cast<const float4*>(&k2s[nbase + 32 + j8 * 4]);

    // prologue: write slab 0 into buffer 0
    {
#pragma unroll
        for (int nn = 0; nn < 8; nn++) {
            uint32_t own = acc[0][nn][0];
            uint32_t rp = __shfl_xor_sync(0xffffffffu, own, 4);
            bufs[sw * SWORDS + 8 * nn + 2 * tq + e0] = __byte_perm(own, rp, psel);
        }
    }

#pragma unroll
    for (int s = 0; s < 8; s++) {
        __syncwarp();
        const int mm = s >> 1;
        const int h = s & 1;
        const int rowb = mbase + mm * 16 + h * 8;

        // reader loads for slab s (issue first: long latency)
        uint32_t* rb = bufs + (s & 3) * BUFW;
        uint4 w0 = *reinterpret_cast<const uint4*>(&rb[sr * SWORDS + j8 * 4]);
        uint4 w1 = *reinterpret_cast<const uint4*>(&rb[sr * SWORDS + (j8 + 8) * 4]);

        // writer for slab s+1 into next buffer (fills the LDS shadow)
        if (s < 7) {
            const int mm2 = (s + 1) >> 1;
            const int h2 = (s + 1) & 1;
            uint32_t* wb = bufs + ((s + 1) & 3) * BUFW;
#pragma unroll
            for (int nn = 0; nn < 8; nn++) {
                uint32_t own = acc[mm2][nn][h2];
                uint32_t rp = __shfl_xor_sync(0xffffffffu, own, 4);
                wb[sw * SWORDS + 8 * nn + 2 * tq + e0] = __byte_perm(own, rp, psel);
            }
        }

        // reader math + STG for slab s
        const float q2e = q2s[rowb + 2 * sr];
        const float q2o = q2s[rowb + 2 * sr + 1];
        {
            float2 c0 = __half22float2(*reinterpret_cast<__half2*>(&w0.x));
            float2 c1 = __half22float2(*reinterpret_cast<__half2*>(&w0.y));
            float2 c2 = __half22float2(*reinterpret_cast<__half2*>(&w0.z));
            float2 c3 = __half22float2(*reinterpret_cast<__half2*>(&w0.w));
            float4 oe, oo;
            oe.x = q2e + k2A.x + c0.x;
            oe.y = q2e + k2A.y + c1.x;
            oe.z = q2e + k2A.z + c2.x;
            oe.w = q2e + k2A.w + c3.x;
            oo.x = q2o + k2A.x + c0.y;
            oo.y = q2o + k2A.y + c1.y;
            oo.z = q2o + k2A.z + c2.y;
            oo.w = q2o + k2A.w + c3.y;
            const size_t rbase = (size_t)bh * LQ + (size_t)(i0 + rowb + 2 * sr);
            const int cg = j0 + nbase + 4 * j8;
            *reinterpret_cast<float4*>(out + rbase * LK + cg) = oe;
            *reinterpret_cast<float4*>(out + (rbase + 1) * LK + cg) = oo;
        }
        {
            float2 c0 = __half22float2(*reinterpret_cast<__half2*>(&w1.x));
            float2 c1 = __half22float2(*reinterpret_cast<__half2*>(&w1.y));
            float2 c2 = __half22float2(*reinterpret_cast<__half2*>(&w1.z));
            float2 c3 = __half22float2(*reinterpret_cast<__half2*>(&w1.w));
            float4 oe, oo;
            oe.x = q2e + k2B.x + c0.x;
            oe.y = q2e + k2B.y + c1.x;
            oe.z = q2e + k2B.z + c2.x;
            oe.w = q2e + k2B.w + c3.x;
            oo.x = q2o + k2B.x + c0.y;
            oo.y = q2o + k2B.y + c1.y;
            oo.z = q2o + k2B.z + c2.y;
            oo.w = q2o + k2B.w + c3.y;
            const size_t rbase = (size_t)bh * LQ + (size_t)(i0 + rowb + 2 * sr);
            const int cg = j0 + nbase + 32 + 4 * j8;
            *reinterpret_cast<float4*>(out + rbase * LK + cg) = oe;
            *reinterpret_cast<float4*>(out + (rbase + 1) * LK + cg) = oo;
        }
    }
}

// ---------------- Launch ----------------

extern "C" void kernel_launch(void* const* d_in, const int* in_sizes, int n_in,
                              void* d_out, int out_size) {
    const float* q = (const float*)d_in[0];   // [4,8,2048,64]
    const float* k = (const float*)d_in[1];   // [4,8,64,2048]
    float* out = (float*)d_out;               // [4,8,2048,2048]
    (void)in_sizes; (void)n_in; (void)out_size;

    cudaFuncSetAttribute(subgauss_kernel,
                         cudaFuncAttributeMaxDynamicSharedMemorySize, SMEM_TOTAL);

    dim3 grid(LK / TN, LQ / TM, 32);  // 8 x 16 x 32
    subgauss_kernel<<<grid, THREADS, SMEM_TOTAL>>>(q, k, out);
}

// round 14
// speedup vs baseline: 1.1140x; 1.1140x over previous
#include <cuda_runtime.h>
#include <cuda_fp16.h>
#include <cstdint>

// ============================================================================
// SubtractionGaussian: out[b,h,i,j] = ||q_i||^2 + ||k_j||^2 - 2 q_i . k_j
// B*H = 32, Lq = Lk = 2048, D = 64, fp32 in/out.
//
// R14 = R9 region (256x256 CTA, loads amortized 2x) + R12 tiles (64x64 warp
//      tiles, -33% ldmatrix) + R11/R12 fp16-acc slab epilogue (unpipelined).
//      8 warps x 2 sequential subtiles cover the 4x4 grid of 64x64 tiles.
//      Phase budget/32K outputs: ~2048 vs R11's ~2816.
// ============================================================================

#define LQ 2048
#define LK 2048
#define DDIM 64
#define TM 256
#define TN 256
#define THREADS 256

#define QROW 72         // halfs per Qs row (9 granules == 1 mod 8 -> ldmatrix conflict-free)
#define KROW 264        // halfs per Ks row (33 granules == 1 mod 8 -> conflict-free)
#define SWORDS 72       // stage super-row pitch in words (== 8 mod 32 -> STS conflict-free)

// dynamic smem layout (bytes)
#define OFF_QS   0                        // 256*72*2  = 36864
#define OFF_KS   36864                    // 64*264*2  = 33792
#define OFF_STG  70656                    // 8 warps * 1152B = 9216 (kpart aliases here)
#define OFF_Q2   79872                    // 256*4     = 1024
#define OFF_K2   80896                    // 256*4     = 1024
#define SMEM_TOTAL 81920

// f16-accum MMA: D,C are 2 regs of half2. Chained D=C.
__device__ __forceinline__ void mma16816_f16(uint32_t* d, const uint32_t* a,
                                             uint32_t b0, uint32_t b1) {
    asm volatile(
        "mma.sync.aligned.m16n8k16.row.col.f16.f16.f16.f16 "
        "{%0,%1}, {%2,%3,%4,%5}, {%6,%7}, {%0,%1};"
        : "+r"(d[0]), "+r"(d[1])
        : "r"(a[0]), "r"(a[1]), "r"(a[2]), "r"(a[3]), "r"(b0), "r"(b1));
}

__device__ __forceinline__ void ldmatrix_x4(uint32_t* r, uint32_t addr) {
    asm volatile("ldmatrix.sync.aligned.m8n8.x4.shared.b16 {%0,%1,%2,%3}, [%4];"
                 : "=r"(r[0]), "=r"(r[1]), "=r"(r[2]), "=r"(r[3]) : "r"(addr));
}

__device__ __forceinline__ void ldmatrix_x4_trans(uint32_t* r, uint32_t addr) {
    asm volatile("ldmatrix.sync.aligned.m8n8.x4.trans.shared.b16 {%0,%1,%2,%3}, [%4];"
                 : "=r"(r[0]), "=r"(r[1]), "=r"(r[2]), "=r"(r[3]) : "r"(addr));
}

__global__ void __launch_bounds__(THREADS, 2)
subgauss_kernel(const float* __restrict__ q,   // [BH, Lq, D]
                const float* __restrict__ k,   // [BH, D, Lk]
                float* __restrict__ out)       // [BH, Lq, Lk]
{
    extern __shared__ __align__(16) char smem[];
    __half* Qs = reinterpret_cast<__half*>(smem + OFF_QS);       // [TM][QROW]
    __half* Ks = reinterpret_cast<__half*>(smem + OFF_KS);       // [DDIM][KROW], holds -2k
    uint32_t* stgall = reinterpret_cast<uint32_t*>(smem + OFF_STG);
    float* kpart = reinterpret_cast<float*>(smem + OFF_STG);     // alias: dead before stage use
    float* q2s = reinterpret_cast<float*>(smem + OFF_Q2);        // [TM]
    float* k2s = reinterpret_cast<float*>(smem + OFF_K2);        // [TN]

    const int tid = threadIdx.x;
    const int lane = tid & 31;
    const int wid = tid >> 5;

    const int bh = blockIdx.z;
    const int i0 = blockIdx.y * TM;
    const int j0 = blockIdx.x * TN;

    // ---- Q load: 256 rows; 2 rows per warp-inst (16 lanes x float4). ----
    {
        const int hi = lane >> 4;
        const int seg2 = lane & 15;
#pragma unroll
        for (int p = 0; p < 16; p++) {
            const int r = wid * 2 + hi + p * 16;
            const float* qrow = q + ((size_t)bh * LQ + (size_t)(i0 + r)) * DDIM;
            float4 v = *reinterpret_cast<const float4*>(qrow + seg2 * 4);
            float s = v.x * v.x + v.y * v.y + v.z * v.z + v.w * v.w;
            s += __shfl_down_sync(0xffffffffu, s, 8, 16);
            s += __shfl_down_sync(0xffffffffu, s, 4, 16);
            s += __shfl_down_sync(0xffffffffu, s, 2, 16);
            s += __shfl_down_sync(0xffffffffu, s, 1, 16);
            if (seg2 == 0) q2s[r] = s;
            __half2 h01 = __floats2half2_rn(v.x, v.y);
            __half2 h23 = __floats2half2_rn(v.z, v.w);
            uint2 u;
            u.x = *reinterpret_cast<uint32_t*>(&h01);
            u.y = *reinterpret_cast<uint32_t*>(&h23);
            *reinterpret_cast<uint2*>(&Qs[r * QROW + seg2 * 4]) = u;
        }
    }

    // ---- K load: 256 cols (two halves); Ks holds -2k; exact fp32 k2 partials. ----
#pragma unroll
    for (int jt = 0; jt < 2; jt++) {
        const float* kb = k + (size_t)bh * DDIM * LK + (size_t)(j0 + jt * 128) + lane * 4;
        float4 ksum = make_float4(0.f, 0.f, 0.f, 0.f);
#pragma unroll
        for (int p = 0; p < 8; p++) {
            const int c = wid + p * 8;
            float4 v = *reinterpret_cast<const float4*>(kb + (size_t)c * LK);
            ksum.x += v.x * v.x; ksum.y += v.y * v.y;
            ksum.z += v.z * v.z; ksum.w += v.w * v.w;
            __half2 h01 = __floats2half2_rn(-2.0f * v.x, -2.0f * v.y);
            __half2 h23 = __floats2half2_rn(-2.0f * v.z, -2.0f * v.w);
            uint2 u;
            u.x = *reinterpret_cast<uint32_t*>(&h01);
            u.y = *reinterpret_cast<uint32_t*>(&h23);
            *reinterpret_cast<uint2*>(&Ks[c * KROW + jt * 128 + lane * 4]) = u;
        }
        *reinterpret_cast<float4*>(&kpart[wid * TN + jt * 128 + lane * 4]) = ksum;
    }
    __syncthreads();

    // ---- k2 reduce: 256 threads, exact fp32 (kpart region dies here). ----
    {
        float s = 0.0f;
#pragma unroll
        for (int w = 0; w < 8; w++) s += kpart[w * TN + tid];
        k2s[tid] = s;
    }
    __syncthreads();
    // -------- no CTA-wide barriers below this line --------

    const int g = lane >> 3;      // ldmatrix quadrant
    const int lr = lane & 7;      // ldmatrix row

    uint32_t* stgW = stgall + wid * 4 * SWORDS;   // warp-private stage
    // writer roles
    const int tq = lane & 3;
    const int sw = (lane >> 2) >> 1;     // super-row
    const int e0 = (lane >> 2) & 1;      // row parity
    const uint32_t psel = e0 ? 0x3276u : 0x5410u;
    // reader roles
    const int sr = lane >> 3;
    const int j8 = lane & 7;

    // ---- 2 sequential 64x64 subtiles per warp over the 4x4 tile grid. ----
#pragma unroll 1
    for (int t = 0; t < 2; t++) {
        const int idx = t * 8 + wid;
        const int mbase = (idx >> 2) * 64;
        const int nbase = (idx & 3) * 64;

        uint32_t acc[4][8][2];
#pragma unroll
        for (int mm = 0; mm < 4; mm++)
#pragma unroll
            for (int nn = 0; nn < 8; nn++) {
                acc[mm][nn][0] = 0u;
                acc[mm][nn][1] = 0u;
            }

        // ---- Mainloop: fp16 accumulate; acc = -2*q.k (K pre-scaled). ----
#pragma unroll
        for (int ks = 0; ks < 4; ks++) {
            uint32_t A[4][4];
#pragma unroll
            for (int mm = 0; mm < 4; mm++) {
                uint32_t addr = (uint32_t)__cvta_generic_to_shared(
                    &Qs[(mbase + mm * 16 + (g & 1) * 8 + lr) * QROW
                        + ks * 16 + (g >> 1) * 8]);
                ldmatrix_x4(A[mm], addr);
            }
#pragma unroll
            for (int e = 0; e < 4; e++) {
                uint32_t B[4];
                uint32_t addr = (uint32_t)__cvta_generic_to_shared(
                    &Ks[(ks * 16 + (g & 1) * 8 + lr) * KROW
                        + nbase + e * 16 + (g >> 1) * 8]);
                ldmatrix_x4_trans(B, addr);
#pragma unroll
                for (int mm = 0; mm < 4; mm++) {
                    mma16816_f16(acc[mm][2 * e],     A[mm], B[0], B[1]);
                    mma16816_f16(acc[mm][2 * e + 1], A[mm], B[2], B[3]);
                }
            }
        }

        // ---- Epilogue: fp16 interleaved stage, 8 slabs (mm x h). ----
        float4 k2A = *reinterpret_cast<const float4*>(&k2s[nbase + j8 * 4]);
        float4 k2B = *reinterpret_cast<const float4*>(&k2s[nbase + 32 + j8 * 4]);

#pragma unroll
        for (int mm = 0; mm < 4; mm++) {
#pragma unroll
            for (int h = 0; h < 2; h++) {
                const int rowb = mbase + mm * 16 + h * 8;
                __syncwarp();
                // writer: row-pair interleave via shfl.xor(4) + PRMT, STS.32
#pragma unroll
                for (int nn = 0; nn < 8; nn++) {
                    uint32_t own = acc[mm][nn][h];
                    uint32_t rp = __shfl_xor_sync(0xffffffffu, own, 4);
                    uint32_t mrg = __byte_perm(own, rp, psel);
                    stgW[sw * SWORDS + 8 * nn + 2 * tq + e0] = mrg;
                }
                __syncwarp();
                // q2 for this slab's row pair
                const float q2e = q2s[rowb + 2 * sr];
                const float q2o = q2s[rowb + 2 * sr + 1];
                // reader: 2x LDS.128 -> cvt -> 4x STG.128 (4 rows x 128B dense)
#pragma unroll
                for (int L = 0; L < 2; L++) {
                    uint4 w = *reinterpret_cast<const uint4*>(
                        &stgW[sr * SWORDS + (j8 + 8 * L) * 4]);
                    float2 c0 = __half22float2(*reinterpret_cast<__half2*>(&w.x));
                    float2 c1 = __half22float2(*reinterpret_cast<__half2*>(&w.y));
                    float2 c2 = __half22float2(*reinterpret_cast<__half2*>(&w.z));
                    float2 c3 = __half22float2(*reinterpret_cast<__half2*>(&w.w));
                    const float4 k2v = L ? k2B : k2A;
                    float4 oe, oo;
                    oe.x = q2e + k2v.x + c0.x;
                    oe.y = q2e + k2v.y + c1.x;
                    oe.z = q2e + k2v.z + c2.x;
                    oe.w = q2e + k2v.w + c3.x;
                    oo.x = q2o + k2v.x + c0.y;
                    oo.y = q2o + k2v.y + c1.y;
                    oo.z = q2o + k2v.z + c2.y;
                    oo.w = q2o + k2v.w + c3.y;
                    const size_t rbase = (size_t)bh * LQ + (size_t)(i0 + rowb + 2 * sr);
                    const int cg = j0 + nbase + 32 * L + 4 * j8;
                    *reinterpret_cast<float4*>(out + rbase * LK + cg) = oe;
                    *reinterpret_cast<float4*>(out + (rbase + 1) * LK + cg) = oo;
                }
            }
        }
    }
}

// ---------------- Launch ----------------

extern "C" void kernel_launch(void* const* d_in, const int* in_sizes, int n_in,
                              void* d_out, int out_size) {
    const float* q = (const float*)d_in[0];   // [4,8,2048,64]
    const float* k = (const float*)d_in[1];   // [4,8,64,2048]
    float* out = (float*)d_out;               // [4,8,2048,2048]
    (void)in_sizes; (void)n_in; (void)out_size;

    cudaFuncSetAttribute(subgauss_kernel,
                         cudaFuncAttributeMaxDynamicSharedMemorySize, SMEM_TOTAL);

    dim3 grid(LK / TN, LQ / TM, 32);  // 8 x 8 x 32
    subgauss_kernel<<<grid, THREADS, SMEM_TOTAL>>>(q, k, out);
}